// round 12
// baseline (speedup 1.0000x reference)
#include <cuda_runtime.h>
#include <cstdint>
#include <cstddef>

// segments: L1: ((m*4+q)<<8) + (o<<1) + s  -> [0,2048), len 256 (q = 256-col chunk, s = 0 pos / 1 neg)
//  W2: 2048+o (128 segs, len 512)  W3: 2176+o (64)  Wout: 2240+o (128)
#define NSEG     2368
#define SEG_W2   2048
#define SEG_W3   2176
#define SEG_WOUT 2240
#define LIST_MAX 655360
#define LIST_CAP 16384
#define ACTS     1.3333333730697632f
#define THREADS  512
#define GRID     512            // 32768 / 64 rows per block

__device__ int d_scale_bits[5];
__device__ int d_cnt[NSEG];
__device__ int d_off[NSEG + 1];
__device__ __align__(16) unsigned short d_list[LIST_MAX];

__global__ void prep_scale(const float* __restrict__ W1a, const float* __restrict__ W1b,
                           const float* __restrict__ W2,  const float* __restrict__ W3,
                           const float* __restrict__ Wout)
{
    __shared__ float red[8];
    int m = blockIdx.x >> 5, part = blockIdx.x & 31;
    const float* W; int n;
    switch (m) {
        case 0: W = W1a;  n = 131072; break;
        case 1: W = W1b;  n = 131072; break;
        case 2: W = W2;   n = 65536;  break;
        case 3: W = W3;   n = 8192;   break;
        default: W = Wout; n = 8192;  break;
    }
    int chunk = n >> 5, lo = part * chunk;
    float mx = 0.0f;
    for (int i = lo + threadIdx.x; i < lo + chunk; i += 256)
        mx = fmaxf(mx, fabsf(W[i]));
    #pragma unroll
    for (int o = 16; o; o >>= 1) mx = fmaxf(mx, __shfl_xor_sync(~0u, mx, o));
    if ((threadIdx.x & 31) == 0) red[threadIdx.x >> 5] = mx;
    __syncthreads();
    if (threadIdx.x < 32) {
        float v = (threadIdx.x < 8) ? red[threadIdx.x] : 0.0f;
        #pragma unroll
        for (int o = 4; o; o >>= 1) v = fmaxf(v, __shfl_xor_sync(~0u, v, o));
        if (threadIdx.x == 0) atomicMax(&d_scale_bits[m], __float_as_int(v));
    }
}

struct SegInfo { const float* rowp; int len; float s; bool l1; int sign; };

__device__ __forceinline__ SegInfo seg_decode(int seg,
    const float* W1a, const float* W1b, const float* W2,
    const float* W3, const float* Wout)
{
    SegInfo r; r.sign = 0;
    if (seg < SEG_W2) {
        int m = seg >> 10, q = (seg >> 8) & 3, o = (seg >> 1) & 127;
        r.sign = seg & 1;
        r.rowp = (m ? W1b : W1a) + o * 1024 + q * 256;
        r.len = 256; r.s = __int_as_float(d_scale_bits[m]); r.l1 = true;
    } else if (seg < SEG_W3) {
        r.rowp = W2 + (seg - SEG_W2) * 512;
        r.len = 512; r.s = __int_as_float(d_scale_bits[2]); r.l1 = false;
    } else if (seg < SEG_WOUT) {
        r.rowp = W3 + (seg - SEG_W3) * 128;
        r.len = 128; r.s = __int_as_float(d_scale_bits[3]); r.l1 = false;
    } else {
        r.rowp = Wout + (seg - SEG_WOUT) * 64;
        r.len = 64; r.s = __int_as_float(d_scale_bits[4]); r.l1 = false;
    }
    return r;
}

__global__ void prep_count(const float* __restrict__ W1a, const float* __restrict__ W1b,
                           const float* __restrict__ W2,  const float* __restrict__ W3,
                           const float* __restrict__ Wout)
{
    int lane = threadIdx.x & 31;
    int seg = blockIdx.x * 8 + (threadIdx.x >> 5);
    if (seg >= NSEG) return;
    SegInfo si = seg_decode(seg, W1a, W1b, W2, W3, Wout);
    int cnt = 0;
    for (int j0 = 0; j0 < si.len; j0 += 32) {
        float q = rintf(__fdiv_rn(si.rowp[j0 + lane], si.s));
        bool nz = si.l1 ? (si.sign ? (q < 0.0f) : (q > 0.0f)) : (q != 0.0f);
        cnt += __popc(__ballot_sync(~0u, nz));
    }
    if (lane == 0) d_cnt[seg] = (cnt + 3) & ~3;   // pad to 4 (0 stays 0)
}

// entries: L1: idx*66 (u16; pad = 16896 = 256*66 -> zero column)
//          W2/W3/Wout: (idx<<2)|cls  (cls 1=+,2=-,0=pad)
__global__ void prep_scanfill(const float* __restrict__ W1a, const float* __restrict__ W1b,
                              const float* __restrict__ W2,  const float* __restrict__ W3,
                              const float* __restrict__ Wout)
{
    __shared__ int s_off[NSEG + 1];
    __shared__ int warpsum[8];
    int tid = threadIdx.x, lane = tid & 31, w = tid >> 5;
    {
        int base = tid * 10, v[10], s = 0;
        #pragma unroll
        for (int k = 0; k < 10; k++) {
            int idx = base + k;
            int c = (idx < NSEG) ? d_cnt[idx] : 0;
            v[k] = s; s += c;
        }
        int incl = s;
        #pragma unroll
        for (int o = 1; o < 32; o <<= 1) {
            int t = __shfl_up_sync(~0u, incl, o);
            if (lane >= o) incl += t;
        }
        if (lane == 31) warpsum[w] = incl;
        __syncthreads();
        if (w == 0 && lane < 8) {
            int ws = warpsum[lane];
            #pragma unroll
            for (int o = 1; o < 8; o <<= 1) {
                int t = __shfl_up_sync(0xffu, ws, o);
                if (lane >= o) ws += t;
            }
            warpsum[lane] = ws;
        }
        __syncthreads();
        int excl = incl - s + (w ? warpsum[w - 1] : 0);
        #pragma unroll
        for (int k = 0; k < 10; k++) {
            int idx = base + k;
            if (idx <= NSEG) s_off[idx] = excl + v[k];
        }
        __syncthreads();
    }
    if (blockIdx.x == 0)
        for (int i = tid; i <= NSEG; i += 256) d_off[i] = s_off[i];

    for (int seg = blockIdx.x * 8 + w; seg < NSEG; seg += gridDim.x * 8) {
        SegInfo si = seg_decode(seg, W1a, W1b, W2, W3, Wout);
        int base = s_off[seg];
        for (int j0 = 0; j0 < si.len; j0 += 32) {
            float q = rintf(__fdiv_rn(si.rowp[j0 + lane], si.s));
            bool nz = si.l1 ? (si.sign ? (q < 0.0f) : (q > 0.0f)) : (q != 0.0f);
            unsigned bal = __ballot_sync(~0u, nz);
            if (nz) {
                int pos = base + __popc(bal & ((1u << lane) - 1u));
                int idx = j0 + lane;
                unsigned e = si.l1 ? (unsigned)(idx * 66)
                                   : (unsigned)((idx << 2) | (q > 0.0f ? 1 : 2));
                d_list[pos] = (unsigned short)e;
            }
            base += __popc(bal);
        }
        unsigned padv = si.l1 ? 16896u : 0u;
        int end = s_off[seg + 1];
        for (int p = base + lane; p < end; p += 32) d_list[p] = (unsigned short)padv;
    }
}

// smem: XS0@0: 257*66*4 = 67848   XS1@67848 (end 135696)
//  H1@135696: 512*66 = 33792 (end 169488)  H2@169488: 8448 (end 177936)
//  H3@177936: 4224 (end 182160)  OFF@182160: 9476 (end 191636, pad->191640)
//  LIST@191640: 16384*2 = 32768 -> total 224408 ; OUTS aliases XS0
#define SMEM_BYTES 224408

__device__ __forceinline__ float quant_relu_q(float y) {
    float qv = rintf(__fdiv_rn(y, ACTS));
    return fminf(fmaxf(qv, 0.0f), 3.0f);
}
__device__ __forceinline__ int csel(unsigned c, int v) {
    int r = (c == 1u) ? v : 0;
    return (c == 2u) ? -v : r;
}
__device__ __forceinline__ unsigned long long packf2(float lo, float hi) {
    unsigned long long r;
    asm("mov.b64 %0, {%1, %2};" : "=l"(r) : "f"(lo), "f"(hi));
    return r;
}
__device__ __forceinline__ void unpackf2(float& lo, float& hi, unsigned long long v) {
    asm("mov.b64 {%0, %1}, %2;" : "=f"(lo), "=f"(hi) : "l"(v));
}
__device__ __forceinline__ void fma2(unsigned long long& a, unsigned long long w,
                                     unsigned long long v) {
    asm("fma.rn.f32x2 %0, %1, %2, %3;" : "=l"(a) : "l"(w), "l"(v), "l"(a));
}

#define L1MAC(b) { \
    unsigned long long v; \
    asm("ld.shared.b64 %0, [%1];" : "=l"(v) : "r"(curb + (b))); \
    fma2(acc, wpx, v); }
#define L1PACK(pk) { \
    unsigned b0 = (pk.x << 2) & 0x3fffcu, b1 = (pk.x >> 14) & 0x3fffcu; \
    unsigned b2 = (pk.y << 2) & 0x3fffcu, b3 = (pk.y >> 14) & 0x3fffcu; \
    L1MAC(b0); L1MAC(b1); L1MAC(b2); L1MAC(b3); }

template<bool USE_SM>
__device__ __forceinline__ void mlp_body(
    unsigned char* smem,
    const float* __restrict__ x,
    const float* __restrict__ b1a, const float* __restrict__ b1b,
    const float* __restrict__ b2,  const float* __restrict__ b3,
    float* __restrict__ out, int row0)
{
    float* xs0 = (float*)(smem);
    float* xs1 = (float*)(smem + 67848);
    unsigned char* h1s = smem + 135696;
    unsigned char* h2s = smem + 169488;
    unsigned char* h3s = smem + 177936;
    int* s_off = (int*)(smem + 182160);
    const unsigned short* lst = USE_SM ? (const unsigned short*)(smem + 191640)
                                       : (const unsigned short*)d_list;
    float* outs = (float*)(smem);   // alias XS0, layout [row][o] stride 132

    const int tid = threadIdx.x, lane = tid & 31, g = tid >> 5;   // g in [0,16)
    const int r2 = lane << 1;
    const int srow = (g << 1) + (lane >> 4);      // rowset 0; rowset 1 = srow + 32
    const int cl = lane & 15;
    const float* xrow0 = x + (size_t)(row0 + srow) * 4096;
    const float* xrow1 = xrow0 + (size_t)32 * 4096;

    const float sc1a = __int_as_float(d_scale_bits[0]);
    const float sc1b = __int_as_float(d_scale_bits[1]);
    const float s2 = __int_as_float(d_scale_bits[2]);
    const float s3 = __int_as_float(d_scale_bits[3]);
    const float s4 = __int_as_float(d_scale_bits[4]);

    // zero column (col 256) in both buffers — L1 pad entries read it
    if (tid < 66) xs0[16896 + tid] = 0.0f;
    else if (tid < 132) xs1[16896 + (tid - 66)] = 0.0f;

    float pf[32];
    #pragma unroll
    for (int k = 0; k < 16; k++) pf[k] = __ldcs(xrow0 + cl + (k << 4));
    #pragma unroll
    for (int k = 0; k < 16; k++) pf[16 + k] = __ldcs(xrow1 + cl + (k << 4));
    #pragma unroll
    for (int k = 0; k < 16; k++) xs0[(cl + (k << 4)) * 66 + srow] = pf[k];
    #pragma unroll
    for (int k = 0; k < 16; k++) xs0[(cl + (k << 4)) * 66 + srow + 32] = pf[16 + k];
    __syncthreads();
    #pragma unroll
    for (int k = 0; k < 16; k++) pf[k] = __ldcs(xrow0 + 256 + cl + (k << 4));
    #pragma unroll
    for (int k = 0; k < 16; k++) pf[16 + k] = __ldcs(xrow1 + 256 + cl + (k << 4));

    unsigned long long accp[8];
    #pragma unroll
    for (int j = 0; j < 8; j++) accp[j] = 0ull;

    // ---- layer 1: 16 tiles [64 rows x 256 cols], pos/neg split, f32x2 FMA ----
    for (int t = 0; t < 16; ++t) {
        const int branch = t >> 2, q = t & 3, m = branch & 1;
        const unsigned curb0 = (unsigned)__cvta_generic_to_shared(
                                   ((t & 1) ? xs1 : xs0)) + (unsigned)(r2 << 2);
        const float sc = m ? sc1b : sc1a;
        const unsigned long long wpos = packf2(sc, sc);
        const unsigned long long wneg = packf2(-sc, -sc);

        #pragma unroll
        for (int j = 0; j < 8; j++) {
            int sb = (((m << 2) + q) << 8) + (((g << 3) + j) << 1);
            int p0 = s_off[sb], p1 = s_off[sb + 1], p2 = s_off[sb + 2];
            unsigned long long acc = accp[j];
            const unsigned curb = curb0;
            {
                unsigned long long wpx = wpos;
                for (int p = p0; p < p1; p += 4) {
                    uint2 pk = *(const uint2*)(lst + p);
                    L1PACK(pk);
                }
                wpx = wneg;
                for (int p = p1; p < p2; p += 4) {
                    uint2 pk = *(const uint2*)(lst + p);
                    L1PACK(pk);
                }
            }
            accp[j] = acc;
        }

        if (q == 3) {
            const float* bb = m ? b1b : b1a;
            #pragma unroll
            for (int j = 0; j < 8; j++) {
                int o = (g << 3) + j;
                float bv = bb[o];
                float a0, a1; unpackf2(a0, a1, accp[j]);
                unsigned c0 = (unsigned)(int)quant_relu_q(a0 + bv);
                unsigned c1 = (unsigned)(int)quant_relu_q(a1 + bv);
                *(unsigned short*)(h1s + (branch * 128 + o) * 66 + r2) =
                    (unsigned short)(c0 | (c1 << 8));
                accp[j] = 0ull;
            }
        }

        if (t + 1 < 16) {
            float* nxt = (t & 1) ? xs0 : xs1;
            #pragma unroll
            for (int k = 0; k < 16; k++)
                nxt[(cl + (k << 4)) * 66 + srow] = pf[k];
            #pragma unroll
            for (int k = 0; k < 16; k++)
                nxt[(cl + (k << 4)) * 66 + srow + 32] = pf[16 + k];
            __syncthreads();
            if (t + 2 < 16) {
                const float* xb0 = xrow0 + (t + 2) * 256;
                const float* xb1 = xrow1 + (t + 2) * 256;
                #pragma unroll
                for (int k = 0; k < 16; k++) pf[k] = __ldcs(xb0 + cl + (k << 4));
                #pragma unroll
                for (int k = 0; k < 16; k++) pf[16 + k] = __ldcs(xb1 + cl + (k << 4));
            }
        }
    }
    __syncthreads();

    // ---- layer 2: 512 -> 128 (8 outputs/warp) ----
    #pragma unroll
    for (int j = 0; j < 8; j++) {
        int o = (g << 3) + j;
        int seg = SEG_W2 + o;
        int p0 = s_off[seg], p1 = s_off[seg + 1];
        int is0 = 0, is1 = 0;
        for (int p = p0; p < p1; p += 4) {
            uint2 pk = *(const uint2*)(lst + p);
            unsigned e0 = pk.x & 0xffffu, e1 = pk.x >> 16;
            unsigned e2 = pk.y & 0xffffu, e3 = pk.y >> 16;
            unsigned c0 = *(const unsigned short*)(h1s + (e0 >> 2) * 66 + r2);
            unsigned c1 = *(const unsigned short*)(h1s + (e1 >> 2) * 66 + r2);
            unsigned c2 = *(const unsigned short*)(h1s + (e2 >> 2) * 66 + r2);
            unsigned c3 = *(const unsigned short*)(h1s + (e3 >> 2) * 66 + r2);
            is0 += csel(e0 & 3u, (int)(c0 & 0xffu)) + csel(e1 & 3u, (int)(c1 & 0xffu))
                 + csel(e2 & 3u, (int)(c2 & 0xffu)) + csel(e3 & 3u, (int)(c3 & 0xffu));
            is1 += csel(e0 & 3u, (int)(c0 >> 8)) + csel(e1 & 3u, (int)(c1 >> 8))
                 + csel(e2 & 3u, (int)(c2 >> 8)) + csel(e3 & 3u, (int)(c3 >> 8));
        }
        float bv = b2[o];
        unsigned q0 = (unsigned)(int)quant_relu_q(fmaf((float)is0 * ACTS, s2, bv));
        unsigned q1 = (unsigned)(int)quant_relu_q(fmaf((float)is1 * ACTS, s2, bv));
        *(unsigned short*)(h2s + o * 66 + r2) = (unsigned short)(q0 | (q1 << 8));
    }
    __syncthreads();

    // ---- layer 3: 128 -> 64 (4 outputs/warp) ----
    #pragma unroll
    for (int j = 0; j < 4; j++) {
        int o = (g << 2) + j;
        int seg = SEG_W3 + o;
        int p0 = s_off[seg], p1 = s_off[seg + 1];
        int is0 = 0, is1 = 0;
        for (int p = p0; p < p1; p += 4) {
            uint2 pk = *(const uint2*)(lst + p);
            unsigned e0 = pk.x & 0xffffu, e1 = pk.x >> 16;
            unsigned e2 = pk.y & 0xffffu, e3 = pk.y >> 16;
            unsigned c0 = *(const unsigned short*)(h2s + (e0 >> 2) * 66 + r2);
            unsigned c1 = *(const unsigned short*)(h2s + (e1 >> 2) * 66 + r2);
            unsigned c2 = *(const unsigned short*)(h2s + (e2 >> 2) * 66 + r2);
            unsigned c3 = *(const unsigned short*)(h2s + (e3 >> 2) * 66 + r2);
            is0 += csel(e0 & 3u, (int)(c0 & 0xffu)) + csel(e1 & 3u, (int)(c1 & 0xffu))
                 + csel(e2 & 3u, (int)(c2 & 0xffu)) + csel(e3 & 3u, (int)(c3 & 0xffu));
            is1 += csel(e0 & 3u, (int)(c0 >> 8)) + csel(e1 & 3u, (int)(c1 >> 8))
                 + csel(e2 & 3u, (int)(c2 >> 8)) + csel(e3 & 3u, (int)(c3 >> 8));
        }
        float bv = b3[o];
        unsigned q0 = (unsigned)(int)quant_relu_q(fmaf((float)is0 * ACTS, s3, bv));
        unsigned q1 = (unsigned)(int)quant_relu_q(fmaf((float)is1 * ACTS, s3, bv));
        *(unsigned short*)(h3s + o * 66 + r2) = (unsigned short)(q0 | (q1 << 8));
    }
    __syncthreads();

    // ---- output layer: 64 -> 128 (8 outputs/warp), no bias ----
    #pragma unroll
    for (int j = 0; j < 8; j++) {
        int o = (g << 3) + j;
        int seg = SEG_WOUT + o;
        int p0 = s_off[seg], p1 = s_off[seg + 1];
        int is0 = 0, is1 = 0;
        for (int p = p0; p < p1; p += 4) {
            uint2 pk = *(const uint2*)(lst + p);
            unsigned e0 = pk.x & 0xffffu, e1 = pk.x >> 16;
            unsigned e2 = pk.y & 0xffffu, e3 = pk.y >> 16;
            unsigned c0 = *(const unsigned short*)(h3s + (e0 >> 2) * 66 + r2);
            unsigned c1 = *(const unsigned short*)(h3s + (e1 >> 2) * 66 + r2);
            unsigned c2 = *(const unsigned short*)(h3s + (e2 >> 2) * 66 + r2);
            unsigned c3 = *(const unsigned short*)(h3s + (e3 >> 2) * 66 + r2);
            is0 += csel(e0 & 3u, (int)(c0 & 0xffu)) + csel(e1 & 3u, (int)(c1 & 0xffu))
                 + csel(e2 & 3u, (int)(c2 & 0xffu)) + csel(e3 & 3u, (int)(c3 & 0xffu));
            is1 += csel(e0 & 3u, (int)(c0 >> 8)) + csel(e1 & 3u, (int)(c1 >> 8))
                 + csel(e2 & 3u, (int)(c2 >> 8)) + csel(e3 & 3u, (int)(c3 >> 8));
        }
        outs[(r2 + 0) * 132 + o] = ((float)is0 * ACTS) * s4;
        outs[(r2 + 1) * 132 + o] = ((float)is1 * ACTS) * s4;
    }
    __syncthreads();

    #pragma unroll
    for (int k = 0; k < 4; k++) {
        int qi = tid + (k << 9);
        int rr = qi >> 5, c4 = qi & 31;
        float4 v = *(const float4*)&outs[rr * 132 + (c4 << 2)];
        *(float4*)&out[(size_t)(row0 + rr) * 128 + (c4 << 2)] = v;
    }
}

__global__ void __launch_bounds__(THREADS, 1) mlp_main(
    const float* __restrict__ x,
    const float* __restrict__ b1a, const float* __restrict__ b1b,
    const float* __restrict__ b2,  const float* __restrict__ b3,
    float* __restrict__ out)
{
    extern __shared__ unsigned char smem[];
    int* s_off = (int*)(smem + 182160);
    unsigned int* s_list = (unsigned int*)(smem + 191640);

    const int tid = threadIdx.x;
    const int row0 = blockIdx.x << 6;

    for (int i = tid; i <= NSEG; i += THREADS) s_off[i] = d_off[i];
    const int total = d_off[NSEG];
    const bool use_sm = (total <= LIST_CAP);
    if (use_sm) {
        const unsigned int* src = (const unsigned int*)d_list;
        int n32 = (total + 1) >> 1;
        for (int i = tid; i < n32; i += THREADS) s_list[i] = src[i];
    }
    __syncthreads();

    if (use_sm) mlp_body<true>(smem, x, b1a, b1b, b2, b3, out, row0);
    else        mlp_body<false>(smem, x, b1a, b1b, b2, b3, out, row0);
}

extern "C" void kernel_launch(void* const* d_in, const int* in_sizes, int n_in,
                              void* d_out, int out_size)
{
    const float* x    = (const float*)d_in[0];
    const float* W1a  = (const float*)d_in[1];
    const float* b1a  = (const float*)d_in[2];
    const float* W1b  = (const float*)d_in[3];
    const float* b1b  = (const float*)d_in[4];
    const float* W2   = (const float*)d_in[5];
    const float* b2   = (const float*)d_in[6];
    const float* W3   = (const float*)d_in[7];
    const float* b3   = (const float*)d_in[8];
    const float* Wout = (const float*)d_in[9];
    float* out = (float*)d_out;

    prep_scale<<<160, 256>>>(W1a, W1b, W2, W3, Wout);
    prep_count<<<NSEG / 8, 256>>>(W1a, W1b, W2, W3, Wout);
    prep_scanfill<<<148, 256>>>(W1a, W1b, W2, W3, Wout);

    cudaFuncSetAttribute(mlp_main, cudaFuncAttributeMaxDynamicSharedMemorySize, SMEM_BYTES);
    mlp_main<<<GRID, THREADS, SMEM_BYTES>>>(x, b1a, b1b, b2, b3, out);
}

// round 13
// speedup vs baseline: 1.3329x; 1.3329x over previous
#include <cuda_runtime.h>
#include <cstdint>
#include <cstddef>

// segments:
//  L1 fused: seg = (m<<8)|(q<<6)|(g<<1)|s  -> [0,512)   (m branch-pair, q 256-col chunk,
//            g warp 0..31, s 0 pos / 1 neg; 4 outputs striped, each padded to Lpad, count = 4*Lpad)
//  W2: 512+o (128 segs, len 512)  W3: 640+o (64)  Wout: 704+o (128)
#define NSEG     832
#define SEG_W2   512
#define SEG_W3   640
#define SEG_WOUT 704
#define LIST_MAX 655360
#define LIST_CAP 20480
#define ACTS     1.3333333730697632f
#define THREADS  1024
#define GRID     512            // 32768 / 64 rows per block

__device__ int d_scale_bits[5];
__device__ int d_cnt[NSEG];
__device__ int d_off[NSEG + 1];
__device__ __align__(16) unsigned short d_list[LIST_MAX];

__global__ void prep_scale(const float* __restrict__ W1a, const float* __restrict__ W1b,
                           const float* __restrict__ W2,  const float* __restrict__ W3,
                           const float* __restrict__ Wout)
{
    __shared__ float red[8];
    int m = blockIdx.x >> 5, part = blockIdx.x & 31;
    const float* W; int n;
    switch (m) {
        case 0: W = W1a;  n = 131072; break;
        case 1: W = W1b;  n = 131072; break;
        case 2: W = W2;   n = 65536;  break;
        case 3: W = W3;   n = 8192;   break;
        default: W = Wout; n = 8192;  break;
    }
    int chunk = n >> 5, lo = part * chunk;
    float mx = 0.0f;
    for (int i = lo + threadIdx.x; i < lo + chunk; i += 256)
        mx = fmaxf(mx, fabsf(W[i]));
    #pragma unroll
    for (int o = 16; o; o >>= 1) mx = fmaxf(mx, __shfl_xor_sync(~0u, mx, o));
    if ((threadIdx.x & 31) == 0) red[threadIdx.x >> 5] = mx;
    __syncthreads();
    if (threadIdx.x < 32) {
        float v = (threadIdx.x < 8) ? red[threadIdx.x] : 0.0f;
        #pragma unroll
        for (int o = 4; o; o >>= 1) v = fmaxf(v, __shfl_xor_sync(~0u, v, o));
        if (threadIdx.x == 0) atomicMax(&d_scale_bits[m], __float_as_int(v));
    }
}

// layer segs decode (seg >= SEG_W2)
struct LSeg { const float* rowp; int len; float s; };
__device__ __forceinline__ LSeg lseg_decode(int seg, const float* W2,
                                            const float* W3, const float* Wout)
{
    LSeg r;
    if (seg < SEG_W3) {
        r.rowp = W2 + (seg - SEG_W2) * 512; r.len = 512;
        r.s = __int_as_float(d_scale_bits[2]);
    } else if (seg < SEG_WOUT) {
        r.rowp = W3 + (seg - SEG_W3) * 128; r.len = 128;
        r.s = __int_as_float(d_scale_bits[3]);
    } else {
        r.rowp = Wout + (seg - SEG_WOUT) * 64; r.len = 64;
        r.s = __int_as_float(d_scale_bits[4]);
    }
    return r;
}

__global__ void prep_count(const float* __restrict__ W1a, const float* __restrict__ W1b,
                           const float* __restrict__ W2,  const float* __restrict__ W3,
                           const float* __restrict__ Wout)
{
    int lane = threadIdx.x & 31;
    int seg = blockIdx.x * 8 + (threadIdx.x >> 5);
    if (seg >= NSEG) return;
    if (seg < SEG_W2) {
        int m = seg >> 8, q = (seg >> 6) & 3, g = (seg >> 1) & 31, s = seg & 1;
        float sc = __int_as_float(d_scale_bits[m]);
        const float* base = (m ? W1b : W1a) + q * 256;
        int Lmax = 0;
        for (int j = 0; j < 4; j++) {
            const float* rowp = base + (size_t)((g << 2) + j) * 1024;
            int cnt = 0;
            for (int j0 = 0; j0 < 256; j0 += 32) {
                float qv = rintf(__fdiv_rn(rowp[j0 + lane], sc));
                bool nz = s ? (qv < 0.0f) : (qv > 0.0f);
                cnt += __popc(__ballot_sync(~0u, nz));
            }
            Lmax = max(Lmax, cnt);
        }
        if (lane == 0) d_cnt[seg] = 4 * ((Lmax + 1) & ~1);
    } else {
        LSeg si = lseg_decode(seg, W2, W3, Wout);
        int cnt = 0;
        for (int j0 = 0; j0 < si.len; j0 += 32) {
            float qv = rintf(__fdiv_rn(si.rowp[j0 + lane], si.s));
            cnt += __popc(__ballot_sync(~0u, qv != 0.0f));
        }
        if (lane == 0) d_cnt[seg] = (cnt + 3) & ~3;
    }
}

// entries: L1 fused: idx*132 (u16; pad = 33792 -> zero column word 16896)
//          layers: (idx<<2)|cls (cls 1=+,2=-,0=pad)
__global__ void prep_scanfill(const float* __restrict__ W1a, const float* __restrict__ W1b,
                              const float* __restrict__ W2,  const float* __restrict__ W3,
                              const float* __restrict__ Wout)
{
    __shared__ int s_off[NSEG + 1];
    __shared__ int warpsum[8];
    int tid = threadIdx.x, lane = tid & 31, w = tid >> 5;
    {
        int base = tid * 4, v[4], s = 0;
        #pragma unroll
        for (int k = 0; k < 4; k++) {
            int idx = base + k;
            int c = (idx < NSEG) ? d_cnt[idx] : 0;
            v[k] = s; s += c;
        }
        int incl = s;
        #pragma unroll
        for (int o = 1; o < 32; o <<= 1) {
            int t = __shfl_up_sync(~0u, incl, o);
            if (lane >= o) incl += t;
        }
        if (lane == 31) warpsum[w] = incl;
        __syncthreads();
        if (w == 0 && lane < 8) {
            int ws = warpsum[lane];
            #pragma unroll
            for (int o = 1; o < 8; o <<= 1) {
                int t = __shfl_up_sync(0xffu, ws, o);
                if (lane >= o) ws += t;
            }
            warpsum[lane] = ws;
        }
        __syncthreads();
        int excl = incl - s + (w ? warpsum[w - 1] : 0);
        #pragma unroll
        for (int k = 0; k < 4; k++) {
            int idx = base + k;
            if (idx <= NSEG) s_off[idx] = excl + v[k];
        }
        __syncthreads();
    }
    if (blockIdx.x == 0)
        for (int i = tid; i <= NSEG; i += 256) d_off[i] = s_off[i];

    for (int seg = blockIdx.x * 8 + w; seg < NSEG; seg += gridDim.x * 8) {
        int base = s_off[seg];
        if (seg < SEG_W2) {
            int m = seg >> 8, q = (seg >> 6) & 3, g = (seg >> 1) & 31, s = seg & 1;
            float sc = __int_as_float(d_scale_bits[m]);
            int Lpad = (s_off[seg + 1] - base) >> 2;
            const float* wb = (m ? W1b : W1a) + q * 256;
            for (int j = 0; j < 4; j++) {
                const float* rowp = wb + (size_t)((g << 2) + j) * 1024;
                int i = 0;
                for (int j0 = 0; j0 < 256; j0 += 32) {
                    float qv = rintf(__fdiv_rn(rowp[j0 + lane], sc));
                    bool nz = s ? (qv < 0.0f) : (qv > 0.0f);
                    unsigned bal = __ballot_sync(~0u, nz);
                    if (nz) {
                        int pos = i + __popc(bal & ((1u << lane) - 1u));
                        d_list[base + pos * 4 + j] = (unsigned short)((j0 + lane) * 132);
                    }
                    i += __popc(bal);
                }
                for (int p = i + lane; p < Lpad; p += 32)
                    d_list[base + p * 4 + j] = (unsigned short)33792;
            }
        } else {
            LSeg si = lseg_decode(seg, W2, W3, Wout);
            int b = base;
            for (int j0 = 0; j0 < si.len; j0 += 32) {
                float qv = rintf(__fdiv_rn(si.rowp[j0 + lane], si.s));
                bool nz = (qv != 0.0f);
                unsigned bal = __ballot_sync(~0u, nz);
                if (nz) {
                    int pos = b + __popc(bal & ((1u << lane) - 1u));
                    d_list[pos] = (unsigned short)(((j0 + lane) << 2) | (qv > 0.0f ? 1 : 2));
                }
                b += __popc(bal);
            }
            int end = s_off[seg + 1];
            for (int p = b + lane; p < end; p += 32) d_list[p] = 0;
        }
    }
}

// smem: XS0@0: 257*66*4 = 67848   XS1@67848 (end 135696)
//  H1@135696: 512*66 = 33792 (end 169488)  H2@169488: 8448 (end 177936)
//  H3@177936: 4224 (end 182160)  OFF@182160: 833*4 = 3332 (end 185492 -> pad 185504)
//  LIST@185504: 20480*2 = 40960 -> total 226464 ; OUTS aliases XS0
#define SMEM_BYTES 226464

__device__ __forceinline__ float quant_relu_q(float y) {
    float qv = rintf(__fdiv_rn(y, ACTS));
    return fminf(fmaxf(qv, 0.0f), 3.0f);
}
__device__ __forceinline__ int csel(unsigned c, int v) {
    int r = (c == 1u) ? v : 0;
    return (c == 2u) ? -v : r;
}
__device__ __forceinline__ unsigned long long packf2(float lo, float hi) {
    unsigned long long r;
    asm("mov.b64 %0, {%1, %2};" : "=l"(r) : "f"(lo), "f"(hi));
    return r;
}
__device__ __forceinline__ void unpackf2(float& lo, float& hi, unsigned long long v) {
    asm("mov.b64 {%0, %1}, %2;" : "=f"(lo), "=f"(hi) : "l"(v));
}
__device__ __forceinline__ void fma2(unsigned long long& a, unsigned long long w,
                                     unsigned long long v) {
    asm("fma.rn.f32x2 %0, %1, %2, %3;" : "=l"(a) : "l"(w), "l"(v), "l"(a));
}

// one striped entry -> one accumulator (static index)
#define FE(acc, ev) { \
    unsigned long long v_; \
    asm("ld.shared.b64 %0, [%1];" : "=l"(v_) : "r"(curb + ((ev) << 1))); \
    fma2(acc, wpx, v_); }
// one LDS.128 = 8 entries = 2 stripes of 4 outputs
#define L1ITER(pk) { \
    FE(t0, pk.x & 0xffffu); FE(t1, pk.x >> 16); \
    FE(t2, pk.y & 0xffffu); FE(t3, pk.y >> 16); \
    FE(t0, pk.z & 0xffffu); FE(t1, pk.z >> 16); \
    FE(t2, pk.w & 0xffffu); FE(t3, pk.w >> 16); }

template<bool USE_SM>
__device__ __forceinline__ void mlp_body(
    unsigned char* smem,
    const float* __restrict__ x,
    const float* __restrict__ b1a, const float* __restrict__ b1b,
    const float* __restrict__ b2,  const float* __restrict__ b3,
    float* __restrict__ out, int row0)
{
    float* xs0 = (float*)(smem);
    float* xs1 = (float*)(smem + 67848);
    unsigned char* h1s = smem + 135696;
    unsigned char* h2s = smem + 169488;
    unsigned char* h3s = smem + 177936;
    int* s_off = (int*)(smem + 182160);
    const unsigned short* lst = USE_SM ? (const unsigned short*)(smem + 185504)
                                       : (const unsigned short*)d_list;
    float* outs = (float*)(smem);   // alias XS0, layout [row][o] stride 132

    const int tid = threadIdx.x, lane = tid & 31, g = tid >> 5;
    const int r2 = lane << 1;
    const int srow = (g << 1) + (lane >> 4);
    const int cl = lane & 15;
    const float* xrow = x + (size_t)(row0 + srow) * 4096;

    const float sc1a = __int_as_float(d_scale_bits[0]);
    const float sc1b = __int_as_float(d_scale_bits[1]);
    const float s2 = __int_as_float(d_scale_bits[2]);
    const float s3 = __int_as_float(d_scale_bits[3]);
    const float s4 = __int_as_float(d_scale_bits[4]);

    // zero column (col 256, word 16896) in both buffers — pad entries read it
    if (tid < 66) xs0[16896 + tid] = 0.0f;
    else if (tid < 132) xs1[16896 + (tid - 66)] = 0.0f;

    float pf[16];
    #pragma unroll
    for (int k = 0; k < 16; k++) pf[k] = __ldcs(xrow + cl + (k << 4));
    #pragma unroll
    for (int k = 0; k < 16; k++) xs0[(cl + (k << 4)) * 66 + srow] = pf[k];
    __syncthreads();
    #pragma unroll
    for (int k = 0; k < 16; k++) pf[k] = __ldcs(xrow + 256 + cl + (k << 4));

    unsigned long long accp[4];
    #pragma unroll
    for (int j = 0; j < 4; j++) accp[j] = 0ull;

    // ---- layer 1: 16 tiles [64 rows x 256 cols], fused striped lists ----
    for (int t = 0; t < 16; ++t) {
        const int branch = t >> 2, q = t & 3, m = branch & 1;
        const unsigned curb = (unsigned)__cvta_generic_to_shared(
                                  ((t & 1) ? xs1 : xs0)) + (unsigned)(r2 << 2);
        const float sc = m ? sc1b : sc1a;
        const unsigned long long wpos = packf2(sc, sc);
        const unsigned long long wneg = packf2(-sc, -sc);

        {
            int sb = (m << 8) + (q << 6) + (g << 1);
            int p0 = s_off[sb], p1 = s_off[sb + 1], p2 = s_off[sb + 2];
            unsigned long long t0 = accp[0], t1 = accp[1], t2 = accp[2], t3 = accp[3];
            unsigned long long wpx = wpos;
            for (int p = p0; p < p1; p += 8) {
                uint4 pk = *(const uint4*)(lst + p);
                L1ITER(pk);
            }
            wpx = wneg;
            for (int p = p1; p < p2; p += 8) {
                uint4 pk = *(const uint4*)(lst + p);
                L1ITER(pk);
            }
            accp[0] = t0; accp[1] = t1; accp[2] = t2; accp[3] = t3;
        }

        if (q == 3) {
            const float* bb = m ? b1b : b1a;
            #pragma unroll
            for (int j = 0; j < 4; j++) {
                int o = (g << 2) + j;
                float bv = bb[o];
                float a0, a1; unpackf2(a0, a1, accp[j]);
                unsigned c0 = (unsigned)(int)quant_relu_q(a0 + bv);
                unsigned c1 = (unsigned)(int)quant_relu_q(a1 + bv);
                *(unsigned short*)(h1s + (branch * 128 + o) * 66 + r2) =
                    (unsigned short)(c0 | (c1 << 8));
                accp[j] = 0ull;
            }
        }

        if (t + 1 < 16) {
            float* nxt = (t & 1) ? xs0 : xs1;
            #pragma unroll
            for (int k = 0; k < 16; k++)
                nxt[(cl + (k << 4)) * 66 + srow] = pf[k];
            __syncthreads();
            if (t + 2 < 16) {
                const float* xb = xrow + (t + 2) * 256;
                #pragma unroll
                for (int k = 0; k < 16; k++)
                    pf[k] = __ldcs(xb + cl + (k << 4));
            }
        }
    }
    __syncthreads();

    // ---- layer 2: 512 -> 128 ----
    #pragma unroll
    for (int j = 0; j < 4; j++) {
        int o = (g << 2) + j;
        int seg = SEG_W2 + o;
        int p0 = s_off[seg], p1 = s_off[seg + 1];
        int is0 = 0, is1 = 0;
        for (int p = p0; p < p1; p += 4) {
            uint2 pk = *(const uint2*)(lst + p);
            unsigned e0 = pk.x & 0xffffu, e1 = pk.x >> 16;
            unsigned e2 = pk.y & 0xffffu, e3 = pk.y >> 16;
            unsigned c0 = *(const unsigned short*)(h1s + (e0 >> 2) * 66 + r2);
            unsigned c1 = *(const unsigned short*)(h1s + (e1 >> 2) * 66 + r2);
            unsigned c2 = *(const unsigned short*)(h1s + (e2 >> 2) * 66 + r2);
            unsigned c3 = *(const unsigned short*)(h1s + (e3 >> 2) * 66 + r2);
            is0 += csel(e0 & 3u, (int)(c0 & 0xffu)) + csel(e1 & 3u, (int)(c1 & 0xffu))
                 + csel(e2 & 3u, (int)(c2 & 0xffu)) + csel(e3 & 3u, (int)(c3 & 0xffu));
            is1 += csel(e0 & 3u, (int)(c0 >> 8)) + csel(e1 & 3u, (int)(c1 >> 8))
                 + csel(e2 & 3u, (int)(c2 >> 8)) + csel(e3 & 3u, (int)(c3 >> 8));
        }
        float bv = b2[o];
        unsigned q0 = (unsigned)(int)quant_relu_q(fmaf((float)is0 * ACTS, s2, bv));
        unsigned q1 = (unsigned)(int)quant_relu_q(fmaf((float)is1 * ACTS, s2, bv));
        *(unsigned short*)(h2s + o * 66 + r2) = (unsigned short)(q0 | (q1 << 8));
    }
    __syncthreads();

    // ---- layer 3: 128 -> 64 ----
    #pragma unroll
    for (int j = 0; j < 2; j++) {
        int o = (g << 1) + j;
        int seg = SEG_W3 + o;
        int p0 = s_off[seg], p1 = s_off[seg + 1];
        int is0 = 0, is1 = 0;
        for (int p = p0; p < p1; p += 4) {
            uint2 pk = *(const uint2*)(lst + p);
            unsigned e0 = pk.x & 0xffffu, e1 = pk.x >> 16;
            unsigned e2 = pk.y & 0xffffu, e3 = pk.y >> 16;
            unsigned c0 = *(const unsigned short*)(h2s + (e0 >> 2) * 66 + r2);
            unsigned c1 = *(const unsigned short*)(h2s + (e1 >> 2) * 66 + r2);
            unsigned c2 = *(const unsigned short*)(h2s + (e2 >> 2) * 66 + r2);
            unsigned c3 = *(const unsigned short*)(h2s + (e3 >> 2) * 66 + r2);
            is0 += csel(e0 & 3u, (int)(c0 & 0xffu)) + csel(e1 & 3u, (int)(c1 & 0xffu))
                 + csel(e2 & 3u, (int)(c2 & 0xffu)) + csel(e3 & 3u, (int)(c3 & 0xffu));
            is1 += csel(e0 & 3u, (int)(c0 >> 8)) + csel(e1 & 3u, (int)(c1 >> 8))
                 + csel(e2 & 3u, (int)(c2 >> 8)) + csel(e3 & 3u, (int)(c3 >> 8));
        }
        float bv = b3[o];
        unsigned q0 = (unsigned)(int)quant_relu_q(fmaf((float)is0 * ACTS, s3, bv));
        unsigned q1 = (unsigned)(int)quant_relu_q(fmaf((float)is1 * ACTS, s3, bv));
        *(unsigned short*)(h3s + o * 66 + r2) = (unsigned short)(q0 | (q1 << 8));
    }
    __syncthreads();

    // ---- output layer: 64 -> 128, no bias ----
    #pragma unroll
    for (int j = 0; j < 4; j++) {
        int o = (g << 2) + j;
        int seg = SEG_WOUT + o;
        int p0 = s_off[seg], p1 = s_off[seg + 1];
        int is0 = 0, is1 = 0;
        for (int p = p0; p < p1; p += 4) {
            uint2 pk = *(const uint2*)(lst + p);
            unsigned e0 = pk.x & 0xffffu, e1 = pk.x >> 16;
            unsigned e2 = pk.y & 0xffffu, e3 = pk.y >> 16;
            unsigned c0 = *(const unsigned short*)(h3s + (e0 >> 2) * 66 + r2);
            unsigned c1 = *(const unsigned short*)(h3s + (e1 >> 2) * 66 + r2);
            unsigned c2 = *(const unsigned short*)(h3s + (e2 >> 2) * 66 + r2);
            unsigned c3 = *(const unsigned short*)(h3s + (e3 >> 2) * 66 + r2);
            is0 += csel(e0 & 3u, (int)(c0 & 0xffu)) + csel(e1 & 3u, (int)(c1 & 0xffu))
                 + csel(e2 & 3u, (int)(c2 & 0xffu)) + csel(e3 & 3u, (int)(c3 & 0xffu));
            is1 += csel(e0 & 3u, (int)(c0 >> 8)) + csel(e1 & 3u, (int)(c1 >> 8))
                 + csel(e2 & 3u, (int)(c2 >> 8)) + csel(e3 & 3u, (int)(c3 >> 8));
        }
        outs[(r2 + 0) * 132 + o] = ((float)is0 * ACTS) * s4;
        outs[(r2 + 1) * 132 + o] = ((float)is1 * ACTS) * s4;
    }
    __syncthreads();

    #pragma unroll
    for (int k = 0; k < 2; k++) {
        int qi = tid + (k << 10);
        int rr = qi >> 5, c4 = qi & 31;
        float4 v = *(const float4*)&outs[rr * 132 + (c4 << 2)];
        *(float4*)&out[(size_t)(row0 + rr) * 128 + (c4 << 2)] = v;
    }
}

__global__ void __launch_bounds__(THREADS, 1) mlp_main(
    const float* __restrict__ x,
    const float* __restrict__ b1a, const float* __restrict__ b1b,
    const float* __restrict__ b2,  const float* __restrict__ b3,
    float* __restrict__ out)
{
    extern __shared__ unsigned char smem[];
    int* s_off = (int*)(smem + 182160);
    unsigned int* s_list = (unsigned int*)(smem + 185504);

    const int tid = threadIdx.x;
    const int row0 = blockIdx.x << 6;

    for (int i = tid; i <= NSEG; i += THREADS) s_off[i] = d_off[i];
    const int total = d_off[NSEG];
    const bool use_sm = (total <= LIST_CAP);
    if (use_sm) {
        const unsigned int* src = (const unsigned int*)d_list;
        int n32 = (total + 1) >> 1;
        for (int i = tid; i < n32; i += THREADS) s_list[i] = src[i];
    }
    __syncthreads();

    if (use_sm) mlp_body<true>(smem, x, b1a, b1b, b2, b3, out, row0);
    else        mlp_body<false>(smem, x, b1a, b1b, b2, b3, out, row0);
}

extern "C" void kernel_launch(void* const* d_in, const int* in_sizes, int n_in,
                              void* d_out, int out_size)
{
    const float* x    = (const float*)d_in[0];
    const float* W1a  = (const float*)d_in[1];
    const float* b1a  = (const float*)d_in[2];
    const float* W1b  = (const float*)d_in[3];
    const float* b1b  = (const float*)d_in[4];
    const float* W2   = (const float*)d_in[5];
    const float* b2   = (const float*)d_in[6];
    const float* W3   = (const float*)d_in[7];
    const float* b3   = (const float*)d_in[8];
    const float* Wout = (const float*)d_in[9];
    float* out = (float*)d_out;

    prep_scale<<<160, 256>>>(W1a, W1b, W2, W3, Wout);
    prep_count<<<NSEG / 8, 256>>>(W1a, W1b, W2, W3, Wout);
    prep_scanfill<<<148, 256>>>(W1a, W1b, W2, W3, Wout);

    cudaFuncSetAttribute(mlp_main, cudaFuncAttributeMaxDynamicSharedMemorySize, SMEM_BYTES);
    mlp_main<<<GRID, THREADS, SMEM_BYTES>>>(x, b1a, b1b, b2, b3, out);
}

// round 15
// speedup vs baseline: 1.4514x; 1.0889x over previous
#include <cuda_runtime.h>
#include <cstdint>
#include <cstddef>

// segments:
//  L1 fused striped: seg = (m<<9)|(c<<6)|(g<<1)|s -> [0,1024)
//     m branch-pair, c 128-col chunk 0..7, g warp, s 0 pos/1 neg; 4 outputs striped, count=4*Lpad
//  W2: 1024+o (128, len 512)  W3: 1152+o (64)  Wout: 1216+o (128)
#define NSEG     1344
#define SEG_W2   1024
#define SEG_W3   1152
#define SEG_WOUT 1216
#define LIST_MAX 655360
#define LIST_CAP 22016
#define ACTS     1.3333333730697632f
#define THREADS  1024
#define GRID     512

__device__ int d_scale_bits[5];
__device__ int d_cnt[NSEG];
__device__ int d_off[NSEG + 1];
__device__ __align__(16) unsigned short d_list[LIST_MAX];

__global__ void prep_scale(const float* __restrict__ W1a, const float* __restrict__ W1b,
                           const float* __restrict__ W2,  const float* __restrict__ W3,
                           const float* __restrict__ Wout)
{
    __shared__ float red[8];
    int m = blockIdx.x >> 5, part = blockIdx.x & 31;
    const float* W; int n;
    switch (m) {
        case 0: W = W1a;  n = 131072; break;
        case 1: W = W1b;  n = 131072; break;
        case 2: W = W2;   n = 65536;  break;
        case 3: W = W3;   n = 8192;   break;
        default: W = Wout; n = 8192;  break;
    }
    int chunk = n >> 5, lo = part * chunk;
    float mx = 0.0f;
    for (int i = lo + threadIdx.x; i < lo + chunk; i += 256)
        mx = fmaxf(mx, fabsf(W[i]));
    #pragma unroll
    for (int o = 16; o; o >>= 1) mx = fmaxf(mx, __shfl_xor_sync(~0u, mx, o));
    if ((threadIdx.x & 31) == 0) red[threadIdx.x >> 5] = mx;
    __syncthreads();
    if (threadIdx.x < 32) {
        float v = (threadIdx.x < 8) ? red[threadIdx.x] : 0.0f;
        #pragma unroll
        for (int o = 4; o; o >>= 1) v = fmaxf(v, __shfl_xor_sync(~0u, v, o));
        if (threadIdx.x == 0) atomicMax(&d_scale_bits[m], __float_as_int(v));
    }
}

struct LSeg { const float* rowp; int len; float s; };
__device__ __forceinline__ LSeg lseg_decode(int seg, const float* W2,
                                            const float* W3, const float* Wout)
{
    LSeg r;
    if (seg < SEG_W3) {
        r.rowp = W2 + (seg - SEG_W2) * 512; r.len = 512;
        r.s = __int_as_float(d_scale_bits[2]);
    } else if (seg < SEG_WOUT) {
        r.rowp = W3 + (seg - SEG_W3) * 128; r.len = 128;
        r.s = __int_as_float(d_scale_bits[3]);
    } else {
        r.rowp = Wout + (seg - SEG_WOUT) * 64; r.len = 64;
        r.s = __int_as_float(d_scale_bits[4]);
    }
    return r;
}

__global__ void prep_count(const float* __restrict__ W1a, const float* __restrict__ W1b,
                           const float* __restrict__ W2,  const float* __restrict__ W3,
                           const float* __restrict__ Wout)
{
    int lane = threadIdx.x & 31;
    int seg = blockIdx.x * 8 + (threadIdx.x >> 5);
    if (seg >= NSEG) return;
    if (seg < SEG_W2) {
        int m = seg >> 9, c = (seg >> 6) & 7, g = (seg >> 1) & 31, s = seg & 1;
        float sc = __int_as_float(d_scale_bits[m]);
        const float* base = (m ? W1b : W1a) + c * 128;
        int Lmax = 0;
        for (int j = 0; j < 4; j++) {
            const float* rowp = base + (size_t)((g << 2) + j) * 1024;
            int cnt = 0;
            for (int j0 = 0; j0 < 128; j0 += 32) {
                float qv = rintf(__fdiv_rn(rowp[j0 + lane], sc));
                bool nz = s ? (qv < 0.0f) : (qv > 0.0f);
                cnt += __popc(__ballot_sync(~0u, nz));
            }
            Lmax = max(Lmax, cnt);
        }
        if (lane == 0) d_cnt[seg] = 4 * ((Lmax + 1) & ~1);
    } else {
        LSeg si = lseg_decode(seg, W2, W3, Wout);
        int cnt = 0;
        for (int j0 = 0; j0 < si.len; j0 += 32) {
            float qv = rintf(__fdiv_rn(si.rowp[j0 + lane], si.s));
            cnt += __popc(__ballot_sync(~0u, qv != 0.0f));
        }
        if (lane == 0) d_cnt[seg] = (cnt + 3) & ~3;
    }
}

// entries: L1 fused: idx*66 (pad = 8448 -> zero column); layers: (idx<<2)|cls (1=+,2=-,0=pad)
__global__ void prep_scanfill(const float* __restrict__ W1a, const float* __restrict__ W1b,
                              const float* __restrict__ W2,  const float* __restrict__ W3,
                              const float* __restrict__ Wout)
{
    __shared__ int s_off[NSEG + 1];
    __shared__ int warpsum[8];
    int tid = threadIdx.x, lane = tid & 31, w = tid >> 5;
    {
        int base = tid * 6, v[6], s = 0;
        #pragma unroll
        for (int k = 0; k < 6; k++) {
            int idx = base + k;
            int c = (idx < NSEG) ? d_cnt[idx] : 0;
            v[k] = s; s += c;
        }
        int incl = s;
        #pragma unroll
        for (int o = 1; o < 32; o <<= 1) {
            int t = __shfl_up_sync(~0u, incl, o);
            if (lane >= o) incl += t;
        }
        if (lane == 31) warpsum[w] = incl;
        __syncthreads();
        if (w == 0 && lane < 8) {
            int ws = warpsum[lane];
            #pragma unroll
            for (int o = 1; o < 8; o <<= 1) {
                int t = __shfl_up_sync(0xffu, ws, o);
                if (lane >= o) ws += t;
            }
            warpsum[lane] = ws;
        }
        __syncthreads();
        int excl = incl - s + (w ? warpsum[w - 1] : 0);
        #pragma unroll
        for (int k = 0; k < 6; k++) {
            int idx = base + k;
            if (idx <= NSEG) s_off[idx] = excl + v[k];
        }
        __syncthreads();
    }
    if (blockIdx.x == 0)
        for (int i = tid; i <= NSEG; i += 256) d_off[i] = s_off[i];

    for (int seg = blockIdx.x * 8 + w; seg < NSEG; seg += gridDim.x * 8) {
        int base = s_off[seg];
        if (seg < SEG_W2) {
            int m = seg >> 9, c = (seg >> 6) & 7, g = (seg >> 1) & 31, s = seg & 1;
            float sc = __int_as_float(d_scale_bits[m]);
            int Lpad = (s_off[seg + 1] - base) >> 2;
            const float* wb = (m ? W1b : W1a) + c * 128;
            for (int j = 0; j < 4; j++) {
                const float* rowp = wb + (size_t)((g << 2) + j) * 1024;
                int i = 0;
                for (int j0 = 0; j0 < 128; j0 += 32) {
                    float qv = rintf(__fdiv_rn(rowp[j0 + lane], sc));
                    bool nz = s ? (qv < 0.0f) : (qv > 0.0f);
                    unsigned bal = __ballot_sync(~0u, nz);
                    if (nz) {
                        int pos = i + __popc(bal & ((1u << lane) - 1u));
                        d_list[base + pos * 4 + j] = (unsigned short)((j0 + lane) * 66);
                    }
                    i += __popc(bal);
                }
                for (int p = i + lane; p < Lpad; p += 32)
                    d_list[base + p * 4 + j] = (unsigned short)8448;
            }
        } else {
            LSeg si = lseg_decode(seg, W2, W3, Wout);
            int b = base;
            for (int j0 = 0; j0 < si.len; j0 += 32) {
                float qv = rintf(__fdiv_rn(si.rowp[j0 + lane], si.s));
                bool nz = (qv != 0.0f);
                unsigned bal = __ballot_sync(~0u, nz);
                if (nz) {
                    int pos = b + __popc(bal & ((1u << lane) - 1u));
                    d_list[pos] = (unsigned short)(((j0 + lane) << 2) | (qv > 0.0f ? 1 : 2));
                }
                b += __popc(bal);
            }
            int end = s_off[seg + 1];
            for (int p = b + lane; p < end; p += 32) d_list[p] = 0;
        }
    }
}

// smem: XS 4 buffers @0: 4*129*66*4 = 136224
//  H1@136224: 33792 (end 170016)  H2@170016: 8448 (end 178464)  H3@178464: 4224 (end 182688)
//  OFF@182688: 1345*4 = 5380 (end 188068, pad 188072)
//  MBAR@188072: 64 (end 188136)  LIST@188144 (16-ALIGNED): 22016*2 = 44032 -> total 232176
#define XSBUF   34056
#define H1_OFF  136224
#define H2_OFF  170016
#define H3_OFF  178464
#define OFF_OFF 182688
#define MB_OFF  188072
#define LST_OFF 188144
#define SMEM_BYTES 232176

__device__ __forceinline__ float quant_relu_q(float y) {
    float qv = rintf(__fdiv_rn(y, ACTS));
    return fminf(fmaxf(qv, 0.0f), 3.0f);
}
__device__ __forceinline__ int csel(unsigned c, int v) {
    int r = (c == 1u) ? v : 0;
    return (c == 2u) ? -v : r;
}
__device__ __forceinline__ unsigned long long packf2(float lo, float hi) {
    unsigned long long r;
    asm("mov.b64 %0, {%1, %2};" : "=l"(r) : "f"(lo), "f"(hi));
    return r;
}
__device__ __forceinline__ void unpackf2(float& lo, float& hi, unsigned long long v) {
    asm("mov.b64 {%0, %1}, %2;" : "=f"(lo), "=f"(hi) : "l"(v));
}
__device__ __forceinline__ void fma2(unsigned long long& a, unsigned long long w,
                                     unsigned long long v) {
    asm("fma.rn.f32x2 %0, %1, %2, %3;" : "=l"(a) : "l"(w), "l"(v), "l"(a));
}

#define MB_INIT(a, c) asm volatile("mbarrier.init.shared.b64 [%0], %1;" :: "r"(a), "r"(c) : "memory")
#define MB_ARRIVE(a)  asm volatile("mbarrier.arrive.shared.b64 _, [%0];" :: "r"(a) : "memory")
#define MB_WAIT(a, ph) do { \
    unsigned _m = (a), _p = (ph), _d; \
    asm volatile("{\n\t.reg .pred p;\n\t" \
        "mbarrier.try_wait.parity.acquire.cta.shared::cta.b64 p, [%1], %2;\n\t" \
        "selp.b32 %0, 1, 0, p;\n\t}" : "=r"(_d) : "r"(_m), "r"(_p) : "memory"); \
    if (!_d) { \
        asm volatile("{\n\t.reg .pred P1;\n\t" \
            "WL_%=:\n\t" \
            "mbarrier.try_wait.parity.acquire.cta.shared::cta.b64 P1, [%0], %1, 0x989680;\n\t" \
            "@P1 bra.uni WD_%=;\n\t" \
            "bra.uni WL_%=;\n\t" \
            "WD_%=:\n\t}" :: "r"(_m), "r"(_p) : "memory"); \
    } } while (0)

#define FE(acc, ev) { \
    unsigned long long v_; \
    asm("ld.shared.b64 %0, [%1];" : "=l"(v_) : "r"(curb + ((ev) << 2))); \
    fma2(acc, wpx, v_); }
#define L1ITER(pk) { \
    FE(t0, pk.x & 0xffffu); FE(t1, pk.x >> 16); \
    FE(t2, pk.y & 0xffffu); FE(t3, pk.y >> 16); \
    FE(t0, pk.z & 0xffffu); FE(t1, pk.z >> 16); \
    FE(t2, pk.w & 0xffffu); FE(t3, pk.w >> 16); }

template<bool USE_SM>
__device__ __forceinline__ void mlp_body(
    unsigned char* smem, unsigned smem_sh,
    const float* __restrict__ x,
    const float* __restrict__ b1a, const float* __restrict__ b1b,
    const float* __restrict__ b2,  const float* __restrict__ b3,
    float* __restrict__ out, int row0)
{
    unsigned char* h1s = smem + H1_OFF;
    unsigned char* h2s = smem + H2_OFF;
    unsigned char* h3s = smem + H3_OFF;
    int* s_off = (int*)(smem + OFF_OFF);
    const unsigned short* lst = USE_SM ? (const unsigned short*)(smem + LST_OFF)
                                       : (const unsigned short*)d_list;
    float* outs = (float*)(smem);

    const int tid = threadIdx.x, lane = tid & 31, g = tid >> 5;
    const int r2 = lane << 1;
    const int srow = (g << 1) + (lane >> 4);
    const int cl = lane & 15;
    const float* xrow = x + (size_t)(row0 + srow) * 4096;

    const float sc1a = __int_as_float(d_scale_bits[0]);
    const float sc1b = __int_as_float(d_scale_bits[1]);
    const float s2 = __int_as_float(d_scale_bits[2]);
    const float s3 = __int_as_float(d_scale_bits[3]);
    const float s4 = __int_as_float(d_scale_bits[4]);

    const unsigned mb = smem_sh + MB_OFF;     // FULL[b]=mb+8b, FREE[b]=mb+32+8b

    float pf[8];
    #pragma unroll
    for (int k = 0; k < 8; k++) pf[k] = __ldcs(xrow + cl + (k << 4));
    {
        float* b0 = (float*)smem;
        #pragma unroll
        for (int k = 0; k < 8; k++) b0[(cl + (k << 4)) * 66 + srow] = pf[k];
    }
    __syncwarp();
    if (lane == 0) MB_ARRIVE(mb + 0);
    #pragma unroll
    for (int k = 0; k < 8; k++) pf[k] = __ldcs(xrow + 128 + cl + (k << 4));
    {
        float* b1 = (float*)(smem + XSBUF);
        #pragma unroll
        for (int k = 0; k < 8; k++) b1[(cl + (k << 4)) * 66 + srow] = pf[k];
    }
    __syncwarp();
    if (lane == 0) MB_ARRIVE(mb + 8);
    #pragma unroll
    for (int k = 0; k < 8; k++) pf[k] = __ldcs(xrow + 256 + cl + (k << 4));

    unsigned long long accp[4];
    #pragma unroll
    for (int j = 0; j < 4; j++) accp[j] = 0ull;

    #pragma unroll 1
    for (int c = 0; c < 32; ++c) {
        const int b = c & 3;
        const int m = (c >> 3) & 1, chunk = c & 7;
        MB_WAIT(mb + (b << 3), (c >> 2) & 1);

        const unsigned curb = smem_sh + b * XSBUF + (unsigned)(r2 << 2);
        const float sc = m ? sc1b : sc1a;
        const unsigned long long wpos = packf2(sc, sc);
        const unsigned long long wneg = packf2(-sc, -sc);
        {
            int sb = (m << 9) + (chunk << 6) + (g << 1);
            int p0 = s_off[sb], p1 = s_off[sb + 1], p2 = s_off[sb + 2];
            unsigned long long t0 = accp[0], t1 = accp[1], t2 = accp[2], t3 = accp[3];
            unsigned long long wpx = wpos;
            for (int p = p0; p < p1; p += 8) {
                uint4 pk = *(const uint4*)(lst + p);
                L1ITER(pk);
            }
            wpx = wneg;
            for (int p = p1; p < p2; p += 8) {
                uint4 pk = *(const uint4*)(lst + p);
                L1ITER(pk);
            }
            accp[0] = t0; accp[1] = t1; accp[2] = t2; accp[3] = t3;
        }
        if (chunk == 7) {
            const int branch = c >> 3;
            const float* bb = m ? b1b : b1a;
            #pragma unroll
            for (int j = 0; j < 4; j++) {
                int o = (g << 2) + j;
                float bv = bb[o];
                float a0, a1; unpackf2(a0, a1, accp[j]);
                unsigned c0 = (unsigned)(int)quant_relu_q(a0 + bv);
                unsigned c1 = (unsigned)(int)quant_relu_q(a1 + bv);
                *(unsigned short*)(h1s + (branch * 128 + o) * 66 + r2) =
                    (unsigned short)(c0 | (c1 << 8));
                accp[j] = 0ull;
            }
        }
        __syncwarp();
        if (lane == 0) MB_ARRIVE(mb + 32 + (b << 3));   // FREE[b]

        const int s = c + 2;
        if (s < 32) {
            const int sbuf = s & 3;
            if (s >= 4) MB_WAIT(mb + 32 + (sbuf << 3), ((s >> 2) - 1) & 1);
            float* nxt = (float*)(smem + sbuf * XSBUF);
            #pragma unroll
            for (int k = 0; k < 8; k++)
                nxt[(cl + (k << 4)) * 66 + srow] = pf[k];
            __syncwarp();
            if (lane == 0) MB_ARRIVE(mb + (sbuf << 3));  // FULL[s]
            if (s + 1 < 32) {
                const float* xb = xrow + (s + 1) * 128;
                #pragma unroll
                for (int k = 0; k < 8; k++)
                    pf[k] = __ldcs(xb + cl + (k << 4));
            }
        }
    }
    __syncthreads();

    // ---- layer 2 ----
    #pragma unroll
    for (int j = 0; j < 4; j++) {
        int o = (g << 2) + j;
        int seg = SEG_W2 + o;
        int p0 = s_off[seg], p1 = s_off[seg + 1];
        int is0 = 0, is1 = 0;
        for (int p = p0; p < p1; p += 4) {
            uint2 pk = *(const uint2*)(lst + p);
            unsigned e0 = pk.x & 0xffffu, e1 = pk.x >> 16;
            unsigned e2 = pk.y & 0xffffu, e3 = pk.y >> 16;
            unsigned c0 = *(const unsigned short*)(h1s + (e0 >> 2) * 66 + r2);
            unsigned c1 = *(const unsigned short*)(h1s + (e1 >> 2) * 66 + r2);
            unsigned c2 = *(const unsigned short*)(h1s + (e2 >> 2) * 66 + r2);
            unsigned c3 = *(const unsigned short*)(h1s + (e3 >> 2) * 66 + r2);
            is0 += csel(e0 & 3u, (int)(c0 & 0xffu)) + csel(e1 & 3u, (int)(c1 & 0xffu))
                 + csel(e2 & 3u, (int)(c2 & 0xffu)) + csel(e3 & 3u, (int)(c3 & 0xffu));
            is1 += csel(e0 & 3u, (int)(c0 >> 8)) + csel(e1 & 3u, (int)(c1 >> 8))
                 + csel(e2 & 3u, (int)(c2 >> 8)) + csel(e3 & 3u, (int)(c3 >> 8));
        }
        float bv = b2[o];
        unsigned q0 = (unsigned)(int)quant_relu_q(fmaf((float)is0 * ACTS, s2, bv));
        unsigned q1 = (unsigned)(int)quant_relu_q(fmaf((float)is1 * ACTS, s2, bv));
        *(unsigned short*)(h2s + o * 66 + r2) = (unsigned short)(q0 | (q1 << 8));
    }
    __syncthreads();

    // ---- layer 3 ----
    #pragma unroll
    for (int j = 0; j < 2; j++) {
        int o = (g << 1) + j;
        int seg = SEG_W3 + o;
        int p0 = s_off[seg], p1 = s_off[seg + 1];
        int is0 = 0, is1 = 0;
        for (int p = p0; p < p1; p += 4) {
            uint2 pk = *(const uint2*)(lst + p);
            unsigned e0 = pk.x & 0xffffu, e1 = pk.x >> 16;
            unsigned e2 = pk.y & 0xffffu, e3 = pk.y >> 16;
            unsigned c0 = *(const unsigned short*)(h2s + (e0 >> 2) * 66 + r2);
            unsigned c1 = *(const unsigned short*)(h2s + (e1 >> 2) * 66 + r2);
            unsigned c2 = *(const unsigned short*)(h2s + (e2 >> 2) * 66 + r2);
            unsigned c3 = *(const unsigned short*)(h2s + (e3 >> 2) * 66 + r2);
            is0 += csel(e0 & 3u, (int)(c0 & 0xffu)) + csel(e1 & 3u, (int)(c1 & 0xffu))
                 + csel(e2 & 3u, (int)(c2 & 0xffu)) + csel(e3 & 3u, (int)(c3 & 0xffu));
            is1 += csel(e0 & 3u, (int)(c0 >> 8)) + csel(e1 & 3u, (int)(c1 >> 8))
                 + csel(e2 & 3u, (int)(c2 >> 8)) + csel(e3 & 3u, (int)(c3 >> 8));
        }
        float bv = b3[o];
        unsigned q0 = (unsigned)(int)quant_relu_q(fmaf((float)is0 * ACTS, s3, bv));
        unsigned q1 = (unsigned)(int)quant_relu_q(fmaf((float)is1 * ACTS, s3, bv));
        *(unsigned short*)(h3s + o * 66 + r2) = (unsigned short)(q0 | (q1 << 8));
    }
    __syncthreads();

    // ---- output layer ----
    #pragma unroll
    for (int j = 0; j < 4; j++) {
        int o = (g << 2) + j;
        int seg = SEG_WOUT + o;
        int p0 = s_off[seg], p1 = s_off[seg + 1];
        int is0 = 0, is1 = 0;
        for (int p = p0; p < p1; p += 4) {
            uint2 pk = *(const uint2*)(lst + p);
            unsigned e0 = pk.x & 0xffffu, e1 = pk.x >> 16;
            unsigned e2 = pk.y & 0xffffu, e3 = pk.y >> 16;
            unsigned c0 = *(const unsigned short*)(h3s + (e0 >> 2) * 66 + r2);
            unsigned c1 = *(const unsigned short*)(h3s + (e1 >> 2) * 66 + r2);
            unsigned c2 = *(const unsigned short*)(h3s + (e2 >> 2) * 66 + r2);
            unsigned c3 = *(const unsigned short*)(h3s + (e3 >> 2) * 66 + r2);
            is0 += csel(e0 & 3u, (int)(c0 & 0xffu)) + csel(e1 & 3u, (int)(c1 & 0xffu))
                 + csel(e2 & 3u, (int)(c2 & 0xffu)) + csel(e3 & 3u, (int)(c3 & 0xffu));
            is1 += csel(e0 & 3u, (int)(c0 >> 8)) + csel(e1 & 3u, (int)(c1 >> 8))
                 + csel(e2 & 3u, (int)(c2 >> 8)) + csel(e3 & 3u, (int)(c3 >> 8));
        }
        outs[(r2 + 0) * 132 + o] = ((float)is0 * ACTS) * s4;
        outs[(r2 + 1) * 132 + o] = ((float)is1 * ACTS) * s4;
    }
    __syncthreads();

    #pragma unroll
    for (int k = 0; k < 2; k++) {
        int qi = tid + (k << 10);
        int rr = qi >> 5, c4 = qi & 31;
        float4 v = *(const float4*)&outs[rr * 132 + (c4 << 2)];
        *(float4*)&out[(size_t)(row0 + rr) * 128 + (c4 << 2)] = v;
    }
}

__global__ void __launch_bounds__(THREADS, 1) mlp_main(
    const float* __restrict__ x,
    const float* __restrict__ b1a, const float* __restrict__ b1b,
    const float* __restrict__ b2,  const float* __restrict__ b3,
    float* __restrict__ out)
{
    extern __shared__ unsigned char smem[];
    int* s_off = (int*)(smem + OFF_OFF);
    unsigned int* s_list = (unsigned int*)(smem + LST_OFF);
    unsigned smem_sh = (unsigned)__cvta_generic_to_shared(smem);

    const int tid = threadIdx.x;
    const int row0 = blockIdx.x << 6;

    if (tid < 8) MB_INIT(smem_sh + MB_OFF + (tid << 3), 32);
    // zero column (words 8448..8513) in all 4 buffers
    if (tid >= 32 && tid < 296) {
        int q = tid - 32;
        ((float*)smem)[(q >> 6) * (XSBUF / 4) + 8448 + (q & 63)] = 0.0f;
    }
    if (tid >= 296 && tid < 304)
        ((float*)smem)[((tid - 296) >> 1) * (XSBUF / 4) + 8512 + ((tid - 296) & 1)] = 0.0f;

    for (int i = tid; i <= NSEG; i += THREADS) s_off[i] = d_off[i];
    const int total = d_off[NSEG];
    const bool use_sm = (total <= LIST_CAP);
    if (use_sm) {
        const unsigned int* src = (const unsigned int*)d_list;
        int n32 = (total + 1) >> 1;
        for (int i = tid; i < n32; i += THREADS) s_list[i] = src[i];
    }
    __syncthreads();

    if (use_sm) mlp_body<true>(smem, smem_sh, x, b1a, b1b, b2, b3, out, row0);
    else        mlp_body<false>(smem, smem_sh, x, b1a, b1b, b2, b3, out, row0);
}

extern "C" void kernel_launch(void* const* d_in, const int* in_sizes, int n_in,
                              void* d_out, int out_size)
{
    const float* x    = (const float*)d_in[0];
    const float* W1a  = (const float*)d_in[1];
    const float* b1a  = (const float*)d_in[2];
    const float* W1b  = (const float*)d_in[3];
    const float* b1b  = (const float*)d_in[4];
    const float* W2   = (const float*)d_in[5];
    const float* b2   = (const float*)d_in[6];
    const float* W3   = (const float*)d_in[7];
    const float* b3   = (const float*)d_in[8];
    const float* Wout = (const float*)d_in[9];
    float* out = (float*)d_out;

    prep_scale<<<160, 256>>>(W1a, W1b, W2, W3, Wout);
    prep_count<<<NSEG / 8, 256>>>(W1a, W1b, W2, W3, Wout);
    prep_scanfill<<<148, 256>>>(W1a, W1b, W2, W3, Wout);

    cudaFuncSetAttribute(mlp_main, cudaFuncAttributeMaxDynamicSharedMemorySize, SMEM_BYTES);
    mlp_main<<<GRID, THREADS, SMEM_BYTES>>>(x, b1a, b1b, b2, b3, out);
}